// round 17
// baseline (speedup 1.0000x reference)
#include <cuda_runtime.h>
#include <cuda_bf16.h>

#define Bz 32
#define Nn 384          // H*W = 12*32
#define Cc 512
#define Dd 512
#define Ee 256
#define Vv 600
#define GJ 2048         // 4*D
#define NSTEP 191
#define EOS_TOK 130

// ----------------------------- scratch (device globals, no allocation) ------
__device__ float g_Wv[Bz * Nn * Dd];          // 24 MB   enc @ W_v, precomputed
__device__ float g_gp[16 * Bz * GJ];          // gates partials [ks][b][2048]
__device__ float g_op[16 * Bz * Dd];          // o_t partials [ks][b][d]
__device__ float g_xT[1280 * Bz];             // transposed x: [emb|oprev|hx][b]
__device__ float g_cx[Bz * Dd];
__device__ float g_q[Bz * Dd];
__device__ float g_ctxT[Cc * Bz];             // transposed context [c][b]
__device__ float g_sc[Bz * Nn];               // raw scores
__device__ int   g_tok[NSTEP * Bz];

// grid barrier state
__device__ unsigned g_count = 0;
__device__ volatile unsigned g_gen = 0;

// fast transcendentals
__device__ __forceinline__ float tanh_mufu(float x) {      // 1 MUFU, abs err ~5e-4
    float y;
    asm("tanh.approx.f32 %0, %1;" : "=f"(y) : "f"(x));
    return y;
}
__device__ __forceinline__ float tanh_fast(float x) {      // 2 MUFU, err ~1e-7
    float e = __expf(-2.0f * x);
    return __fdividef(2.0f, 1.0f + e) - 1.0f;
}
__device__ __forceinline__ float sig_fast(float x) {
    return __fdividef(1.0f, 1.0f + __expf(-x));
}

__device__ __forceinline__ void gsync(int nblk) {
    __syncthreads();
    if (threadIdx.x == 0) {
        __threadfence();
        unsigned gen = g_gen;
        unsigned t = atomicInc(&g_count, (unsigned)(nblk - 1)); // wraps at nblk-1
        if (t == (unsigned)(nblk - 1)) {
            __threadfence();
            g_gen = gen + 1;                 // release
        } else {
            while (g_gen == gen) { }         // spin (volatile load)
            __threadfence();                 // acquire
        }
    }
    __syncthreads();
}

// ===================== prologue kernel (unconstrained regs) ==================
__global__ void k_pre(const float* __restrict__ enc, const int* __restrict__ tgt,
                      const float* __restrict__ Wvw)
{
    __shared__ float sh[2048];
    const int tid = threadIdx.x;
    const int job = blockIdx.x;                      // 399 blocks

    if (job < 384) {
        int bm = job >> 2, bn = job & 3;
        int tm = tid / 16, tn = tid % 16;
        float acc[8][8];
#pragma unroll
        for (int i = 0; i < 8; i++)
#pragma unroll
            for (int j = 0; j < 8; j++) acc[i][j] = 0.0f;
        const float* Ag = enc + (size_t)(bm * 128) * 512;
        const float* Bg = Wvw + bn * 128;
        float* As = sh;            // [8][128]
        float* Bs = sh + 1024;     // [8][128]
        for (int k0 = 0; k0 < 512; k0 += 8) {
            {
                int r = tid >> 1, s = tid & 1;
                float4 a = *(const float4*)(Ag + (size_t)r * 512 + k0 + s * 4);
                As[(s * 4 + 0) * 128 + r] = a.x; As[(s * 4 + 1) * 128 + r] = a.y;
                As[(s * 4 + 2) * 128 + r] = a.z; As[(s * 4 + 3) * 128 + r] = a.w;
            }
            {
                int kk = tid >> 5, c4 = tid & 31;
                float4 bv = *(const float4*)(Bg + (size_t)(k0 + kk) * 512 + c4 * 4);
                *(float4*)&Bs[kk * 128 + c4 * 4] = bv;
            }
            __syncthreads();
#pragma unroll
            for (int kk = 0; kk < 8; kk++) {
                float a[8], b[8];
                *(float4*)(a)     = *(float4*)&As[kk * 128 + tm * 8];
                *(float4*)(a + 4) = *(float4*)&As[kk * 128 + tm * 8 + 4];
                *(float4*)(b)     = *(float4*)&Bs[kk * 128 + tn * 8];
                *(float4*)(b + 4) = *(float4*)&Bs[kk * 128 + tn * 8 + 4];
#pragma unroll
                for (int i = 0; i < 8; i++)
#pragma unroll
                    for (int j = 0; j < 8; j++) acc[i][j] += a[i] * b[j];
            }
            __syncthreads();
        }
        float* Cg = g_Wv + (size_t)(bm * 128) * 512 + bn * 128;
#pragma unroll
        for (int i = 0; i < 8; i++) {
            int r = tm * 8 + i;
#pragma unroll
            for (int j = 0; j < 8; j += 4) {
                float4 o = make_float4(acc[i][j], acc[i][j+1], acc[i][j+2], acc[i][j+3]);
                *(float4*)(Cg + (size_t)r * 512 + tn * 8 + j) = o;
            }
        }
    } else if (job == 384) {
        // token precompute (int64/int32 autodetect: int64 high words are 0)
        if (tid == 0) {
            int nz = 0;
            for (int i = 1; i < 64; i += 2) nz |= tgt[i];
            ((int*)sh)[0] = (nz == 0) ? 1 : 0;
        }
        __syncthreads();
        int is64 = ((int*)sh)[0];
        if (tid < Bz) {
            int b = tid, fin = 0;
            g_tok[b] = 0;                            // sos
            for (int t = 0; t < NSTEP - 1; t++) {
                int idx = b * 192 + t + 1;
                int nt = is64 ? tgt[idx * 2] : tgt[idx];
                fin |= (nt == EOS_TOK);
                g_tok[(t + 1) * Bz + b] = fin ? 0 : nt;
            }
        }
    } else {
        int base = (job - 385) * 4096;               // 14 jobs x 4096 = 57344
        for (int i = tid; i < 4096; i += 256) {
            int idx = base + i;
            if (idx < 40960)        g_xT[idx] = 0.0f;   // emb(0)=0, oprev=0, hx=0
            else if (idx < 57344)   g_cx[idx - 40960] = 0.0f;
        }
    }
}

// ===================== persistent step kernel (occ 4) ========================
__global__ void __launch_bounds__(256, 4) k_steps(
    const float* __restrict__ enc, const float* __restrict__ emb,
    const float* __restrict__ Wih, const float* __restrict__ bih,
    const float* __restrict__ Whh, const float* __restrict__ bhh,
    const float* __restrict__ Wh,  const float* __restrict__ vvec,
    const float* __restrict__ Wc,  const float* __restrict__ bc,
    const float* __restrict__ Wout,const float* __restrict__ bout,
    float* __restrict__ out_logits, float* __restrict__ out_alpha, int nblk)
{
    __shared__ float sh[3104];                       // 12.1 KB, reused per phase
    const int tid = threadIdx.x;
    const int bid = blockIdx.x;

    for (int t = 0; t < NSTEP; t++) {

        // ---- A: gates split-K GEMM: 512 jobs (32 jt x 16 ks) ----
        for (int job = bid; job < 512; job += nblk) {
            int jt = job & 31, ks = job >> 5;
            int kbase, klen;
            if (ks < 8) { kbase = ks * 96;             klen = 96; }
            else        { kbase = 768 + (ks - 8) * 64; klen = 64; }
            float* xs = sh;                            // [klen][32] <= 3072
            for (int i4 = tid; i4 < klen * 8; i4 += 256) {
                int kk = i4 >> 3, b4 = i4 & 7;
                float4 v = ((const float4*)(g_xT + (size_t)(kbase + kk) * 32))[b4];
                ((float4*)(xs + kk * 32))[b4] = v;
            }
            __syncthreads();
            int jj = tid & 63, bq = tid >> 6;          // 4 bq x 8 b
            int j = jt * 64 + jj;
            const float* Wp = (ks < 8) ? (Wih + (size_t)kbase * GJ + j)
                                       : (Whh + (size_t)(kbase - 768) * GJ + j);
            float acc[8];
#pragma unroll
            for (int i = 0; i < 8; i++) acc[i] = 0.0f;
#pragma unroll 8
            for (int kk = 0; kk < klen; kk++) {
                float w = Wp[(size_t)kk * GJ];
                float4 x0 = *(float4*)&xs[kk * 32 + bq * 8];
                float4 x1 = *(float4*)&xs[kk * 32 + bq * 8 + 4];
                acc[0] += w * x0.x; acc[1] += w * x0.y; acc[2] += w * x0.z; acc[3] += w * x0.w;
                acc[4] += w * x1.x; acc[5] += w * x1.y; acc[6] += w * x1.z; acc[7] += w * x1.w;
            }
#pragma unroll
            for (int i = 0; i < 8; i++)
                g_gp[((size_t)ks * Bz + bq * 8 + i) * GJ + j] = acc[i];
            __syncthreads();
        }
        gsync(nblk);

        // ---- B: LSTM elementwise (reduce 16 partials) + zero q/ctxT ----
        for (int idx = bid * 256 + tid; idx < 16384; idx += nblk * 256) {
            int d = idx & 511;
            int b = idx >> 9;
            float gi = bih[d] + bhh[d];
            float gf = bih[d + 512] + bhh[d + 512];
            float gg = bih[d + 1024] + bhh[d + 1024];
            float go = bih[d + 1536] + bhh[d + 1536];
#pragma unroll
            for (int s = 0; s < 16; s++) {
                const float* gp = g_gp + ((size_t)s * Bz + b) * GJ;
                gi += gp[d];
                gf += gp[d + 512];
                gg += gp[d + 1024];
                go += gp[d + 1536];
            }
            float c = g_cx[idx];
            c = sig_fast(gf) * c + sig_fast(gi) * tanh_fast(gg);
            float h = sig_fast(go) * tanh_fast(c);
            g_cx[idx] = c;
            g_xT[(768 + d) * 32 + b] = h;            // transposed hx
            g_q[idx] = 0.0f;
            g_ctxT[idx] = 0.0f;
        }
        gsync(nblk);

        // ---- C: q = hx @ W_h: 256 jobs (16 dt x 16 ks of K=32) ----
        for (int job = bid; job < 256; job += nblk) {
            int dt = job & 15, ks = job >> 4;
            float* xs = sh;                            // [32][32]
            {
                int kk = tid >> 3, b4 = tid & 7;
                float4 v = ((const float4*)(g_xT + (size_t)(768 + ks * 32 + kk) * 32))[b4];
                ((float4*)(xs + kk * 32))[b4] = v;
            }
            __syncthreads();
            int dl = tid & 31, bq = tid >> 5;          // 8 bq x 4 b
            int d = dt * 32 + dl;
            const float* Wp = Wh + (size_t)(ks * 32) * Dd + d;
            float acc[4];
#pragma unroll
            for (int i = 0; i < 4; i++) acc[i] = 0.0f;
#pragma unroll 8
            for (int kk = 0; kk < 32; kk++) {
                float w = Wp[(size_t)kk * Dd];
                float4 x0 = *(float4*)&xs[kk * 32 + bq * 4];
                acc[0] += w * x0.x; acc[1] += w * x0.y;
                acc[2] += w * x0.z; acc[3] += w * x0.w;
            }
#pragma unroll
            for (int i = 0; i < 4; i++)
                atomicAdd(&g_q[(bq * 4 + i) * Dd + d], acc[i]);
            __syncthreads();
        }
        gsync(nblk);

        // ---- D: scores: 608 jobs (19 tiles x 32 b), pure MUFU tanh ----
        for (int job = bid; job < 608; job += nblk) {
            int nt = job % 19, b = job / 19;
            float* qs = sh;
            float* vs = sh + 512;
            qs[tid] = g_q[b * Dd + tid];
            qs[tid + 256] = g_q[b * Dd + tid + 256];
            vs[tid] = vvec[tid];
            vs[tid + 256] = vvec[tid + 256];
            __syncthreads();
            int w = tid >> 5, lane = tid & 31;
            int n0 = nt * 20;
            int cnt = (nt == 18) ? 24 : 20;
            const float4* q4 = (const float4*)qs;
            const float4* v4 = (const float4*)vs;
            for (int r = w; r < cnt; r += 8) {
                int n = n0 + r;
                const float4* wv = (const float4*)(g_Wv + (size_t)(b * Nn + n) * Dd);
                float acc = 0.0f;
#pragma unroll
                for (int i = 0; i < 4; i++) {
                    int id = i * 32 + lane;
                    float4 a = wv[id], q = q4[id], v = v4[id];
                    acc += tanh_mufu(a.x + q.x) * v.x;
                    acc += tanh_mufu(a.y + q.y) * v.y;
                    acc += tanh_mufu(a.z + q.z) * v.z;
                    acc += tanh_mufu(a.w + q.w) * v.w;
                }
#pragma unroll
                for (int off = 16; off > 0; off >>= 1)
                    acc += __shfl_xor_sync(0xffffffffu, acc, off);
                if (lane == 0) g_sc[b * Nn + n] = acc;
            }
            __syncthreads();
        }
        gsync(nblk);

        // ---- E: softmax + context + alpha: 512 jobs (16 strips x 32 b) ----
        for (int job = bid; job < 512; job += nblk) {
            int st = job & 15, b = job >> 4;
            float* al = sh;                            // [384]
            float* red = sh + 384;                     // [256]
            float m = -1e30f;
            for (int i = tid; i < Nn; i += 256) {
                float s = g_sc[b * Nn + i];
                al[i] = s;
                m = fmaxf(m, s);
            }
            red[tid] = m; __syncthreads();
            for (int o = 128; o > 0; o >>= 1) {
                if (tid < o) red[tid] = fmaxf(red[tid], red[tid + o]);
                __syncthreads();
            }
            m = red[0];
            __syncthreads();
            float sum = 0.0f;
            for (int i = tid; i < Nn; i += 256) {
                float e = __expf(al[i] - m);
                al[i] = e;
                sum += e;
            }
            red[tid] = sum; __syncthreads();
            for (int o = 128; o > 0; o >>= 1) {
                if (tid < o) red[tid] += red[tid + o];
                __syncthreads();
            }
            float inv = __fdividef(1.0f, red[0]);
            __syncthreads();
            for (int i = tid; i < Nn; i += 256) al[i] *= inv;
            __syncthreads();

            if (st == 0) {
                float* ap = out_alpha + ((size_t)b * NSTEP + t) * Nn;
                for (int i = tid; i < Nn; i += 256) ap[i] = al[i];
            }
            // context partial: strip of 24 n, 2 ways of 12 n
            int c4 = tid & 127, way = tid >> 7;
            const float4* ep = (const float4*)enc + (size_t)b * Nn * 128 + c4;
            float4 acc = make_float4(0.f, 0.f, 0.f, 0.f);
            int n0 = st * 24 + way * 12;
#pragma unroll 4
            for (int n = n0; n < n0 + 12; n++) {
                float a = al[n];
                float4 ev = ep[(size_t)n * 128];
                acc.x += a * ev.x; acc.y += a * ev.y;
                acc.z += a * ev.z; acc.w += a * ev.w;
            }
            int c = c4 * 4;
            atomicAdd(&g_ctxT[(size_t)(c + 0) * 32 + b], acc.x);
            atomicAdd(&g_ctxT[(size_t)(c + 1) * 32 + b], acc.y);
            atomicAdd(&g_ctxT[(size_t)(c + 2) * 32 + b], acc.z);
            atomicAdd(&g_ctxT[(size_t)(c + 3) * 32 + b], acc.w);
            __syncthreads();
        }
        gsync(nblk);

        // ---- F: o_t partials + logits bias init: 331 jobs ----
        for (int job = bid; job < 331; job += nblk) {
            if (job >= 256) {
                int idx = (job - 256) * 256 + tid;     // < 32*600 = 19200
                if (idx < Bz * Vv) {
                    int b = idx / Vv, v = idx % Vv;
                    out_logits[((size_t)b * NSTEP + t) * Vv + v] = bout[v];
                }
            } else {
                // (dt 0..15, ks 0..15): K=64, d-tile 32, all 32 b
                float* xs = sh;                        // [64][32] = 2048
                int dt = job & 15, ks = job >> 4;
                for (int i4 = tid; i4 < 512; i4 += 256) {
                    int kk = i4 >> 3, b4 = i4 & 7;
                    int k = ks * 64 + kk;
                    const float* src = (k < 512) ? (g_xT + (size_t)(768 + k) * 32)
                                                 : (g_ctxT + (size_t)(k - 512) * 32);
                    float4 v = ((const float4*)src)[b4];
                    ((float4*)(xs + kk * 32))[b4] = v;
                }
                __syncthreads();
                int dl = tid & 31, bq = tid >> 5;      // 8 bq x 4 b
                int d = dt * 32 + dl;
                const float* Wp = Wc + (size_t)(ks * 64) * Dd + d;
                float acc[4];
#pragma unroll
                for (int i = 0; i < 4; i++) acc[i] = 0.0f;
#pragma unroll 8
                for (int kk = 0; kk < 64; kk++) {
                    float w = Wp[(size_t)kk * Dd];
                    float4 x0 = *(float4*)&xs[kk * 32 + bq * 4];
                    acc[0] += w * x0.x; acc[1] += w * x0.y;
                    acc[2] += w * x0.z; acc[3] += w * x0.w;
                }
#pragma unroll
                for (int i = 0; i < 4; i++)
                    g_op[((size_t)ks * Bz + bq * 4 + i) * Dd + d] = acc[i];
            }
            __syncthreads();
        }
        gsync(nblk);

        // ---- G: logits + o_prevT persist + embT(t+1) prefetch: 328 jobs ----
        for (int job = bid; job < 328; job += nblk) {
            if (job >= 320) {
                if (t + 1 < NSTEP) {
                    int j8 = job - 320;                // 8 jobs x 32 k-rows
                    for (int i = tid; i < 1024; i += 256) {
                        int k = j8 * 32 + (i >> 5), b = i & 31;
                        int tok = g_tok[(t + 1) * Bz + b];
                        g_xT[k * 32 + b] = emb[tok * Ee + k];
                    }
                }
            } else {
                // (vt 0..9, ds 0..15, bh 0..1): 16 b, K=32
                float* os = sh;                        // [32][20] pitch 20
                int vt = job % 10, ds = (job / 10) & 15, bh = job / 160;
                for (int i = tid; i < 512; i += 256) {
                    int dl = i & 31, bl = i >> 5;      // 32 d x 16 b
                    int gb = bh * 16 + bl;
                    int d = ds * 32 + dl;
                    float s = bc[d];
#pragma unroll
                    for (int p = 0; p < 16; p++)
                        s += g_op[((size_t)p * Bz + gb) * Dd + d];
                    float o = tanh_fast(s);
                    os[dl * 20 + bl] = o;
                    if (vt == 0) g_xT[(size_t)(256 + d) * 32 + gb] = o;   // o_prevT
                }
                __syncthreads();
                int jj = tid & 63, bq = tid >> 6;      // 4 bq x 4 b
                int v = vt * 64 + jj;
                bool ok = (v < Vv);
                const float* Wp = Wout + (size_t)(ds * 32) * Vv + (ok ? v : 0);
                float acc[4];
#pragma unroll
                for (int i = 0; i < 4; i++) acc[i] = 0.0f;
#pragma unroll 8
                for (int kk = 0; kk < 32; kk++) {
                    float w = Wp[(size_t)kk * Vv];
                    float4 x0 = *(float4*)&os[kk * 20 + bq * 4];
                    acc[0] += w * x0.x; acc[1] += w * x0.y;
                    acc[2] += w * x0.z; acc[3] += w * x0.w;
                }
                if (ok) {
#pragma unroll
                    for (int i = 0; i < 4; i++) {
                        int b = bh * 16 + bq * 4 + i;
                        atomicAdd(&out_logits[((size_t)b * NSTEP + t) * Vv + v], acc[i]);
                    }
                }
            }
            __syncthreads();
        }
        gsync(nblk);
    }
}

// ----------------------------- launch ---------------------------------------
extern "C" void kernel_launch(void* const* d_in, const int* in_sizes, int n_in,
                              void* d_out, int out_size) {
    const float* enc  = (const float*)d_in[0];
    const int*   tgt  = (const int*)d_in[1];         // int32 or int64, autodetected
    const float* emb  = (const float*)d_in[2];
    const float* Wih  = (const float*)d_in[3];
    const float* bih  = (const float*)d_in[4];
    const float* Whh  = (const float*)d_in[5];
    const float* bhh  = (const float*)d_in[6];
    const float* Wh   = (const float*)d_in[7];
    const float* Wvw  = (const float*)d_in[8];
    const float* vvec = (const float*)d_in[9];
    const float* Wc   = (const float*)d_in[10];
    const float* bc   = (const float*)d_in[11];
    const float* Wout = (const float*)d_in[12];
    const float* bout = (const float*)d_in[13];

    float* out_logits = (float*)d_out;                           // (32,191,600)
    float* out_alpha  = out_logits + (size_t)Bz * NSTEP * Vv;    // (32,191,384)

    int dev = 0;
    cudaGetDevice(&dev);
    int sms = 148;
    cudaDeviceGetAttribute(&sms, cudaDevAttrMultiProcessorCount, dev);
    int per = 0;
    cudaOccupancyMaxActiveBlocksPerMultiprocessor(&per, k_steps, 256, 0);
    if (per < 1) per = 1;
    if (per > 4) per = 4;
    int nblk = sms * per;                            // one resident wave

    k_pre<<<399, 256>>>(enc, tgt, Wvw);
    k_steps<<<nblk, 256>>>(enc, emb, Wih, bih, Whh, bhh, Wh, vvec,
                           Wc, bc, Wout, bout, out_logits, out_alpha, nblk);
}